// round 15
// baseline (speedup 1.0000x reference)
#include <cuda_runtime.h>

// Problem constants (FullChain_58815282152074): N=4096 nodes, d=16, K=16, B=4
#define MB   1024          // nodes per batch (M)
#define NB   4             // num_batches
#define IG   4             // i's per block

// Scratch: effective bilinear weight WT[d][e][o] and effective bias
__device__ float g_WT[16 * 16 * 16];
__device__ float g_beff[16];

// ---- packed f32x2 helpers (Blackwell FFMA2) ----
__device__ __forceinline__ unsigned long long ffma2(unsigned long long a,
                                                    unsigned long long b,
                                                    unsigned long long c) {
    unsigned long long d;
    asm("fma.rn.f32x2 %0, %1, %2, %3;" : "=l"(d) : "l"(a), "l"(b), "l"(c));
    return d;
}
__device__ __forceinline__ unsigned long long pack2(float lo, float hi) {
    unsigned long long d;
    asm("mov.b64 %0, {%1, %2};"
        : "=l"(d) : "r"(__float_as_uint(lo)), "r"(__float_as_uint(hi)));
    return d;
}
__device__ __forceinline__ float2 unpack2(unsigned long long v) {
    unsigned int lo, hi;
    asm("mov.b64 {%0, %1}, %2;" : "=r"(lo), "=r"(hi) : "l"(v));
    return make_float2(__uint_as_float(lo), __uint_as_float(hi));
}

// ---------------------------------------------------------------------------
// Kernel A: fold W3@W2 into the bilinear form.
//   C[o,k]     = sum_t W3[o,t] * W2[t,k]
//   WT[d,e,o]  = sum_k C[o,k] * W_bil[k,d,e]     (stored [d][e][o])
//   beff[o]    = sum_k C[o,k]*b_bil[k] + sum_t W3[o,t]*b2[t] + b3[o]
// ---------------------------------------------------------------------------
__global__ void prep_kernel(const float* __restrict__ W_bil,
                            const float* __restrict__ b_bil,
                            const float* __restrict__ W2,
                            const float* __restrict__ b2,
                            const float* __restrict__ W3,
                            const float* __restrict__ b3) {
    __shared__ float Cs[256];
    int tid = threadIdx.x;
    {
        int o = tid >> 4, k = tid & 15;
        float s = 0.f;
#pragma unroll
        for (int t = 0; t < 16; ++t) s += W3[o * 16 + t] * W2[t * 16 + k];
        Cs[tid] = s;
    }
    __syncthreads();
    {
        int d = tid >> 4, e = tid & 15;
#pragma unroll
        for (int o = 0; o < 16; ++o) {
            float s = 0.f;
#pragma unroll
            for (int k = 0; k < 16; ++k)
                s += Cs[o * 16 + k] * W_bil[k * 256 + d * 16 + e];
            g_WT[(d * 16 + e) * 16 + o] = s;
        }
    }
    if (tid < 16) {
        int o = tid;
        float s = b3[o];
#pragma unroll
        for (int k = 0; k < 16; ++k) s += Cs[o * 16 + k] * b_bil[k];
#pragma unroll
        for (int t = 0; t < 16; ++t) s += W3[o * 16 + t] * b2[t];
        g_beff[o] = s;
    }
}

// ---------------------------------------------------------------------------
// Kernel B (dual-stream R14 skeleton + e-pair packing R8/R9):
//   One block per (b, group of IG=4 i's).  256 threads, 2 CTAs/SM.
//   Phase 0: stage batch X (1024x16 floats, stride 16, conflict-free:
//            each quarter-warp LDS.128 phase = 2 rows in disjoint halves).
//   Phase 1: T_i[e][o] for 4 i's, PAIR-INTERLEAVED over e:
//            T2sm[ii][e/2][o][2] = {T[e even], T[e odd]}   (256 floats/i).
//   Phase 2: lane = (j-slot = lane>>2, o-quad = lane&3); T2 for the o-quad
//            in 32 u64 regs (Ta..Td[8]).  Each iteration processes TWO j's
//            (stream A = warp rows [0,64), B = [64,128)): all 8 LDS.128
//            issue before either chain; 8 interleaved FFMA2 chains; x pairs
//            come straight from the ulonglong2 loads (ZERO pack2).  Bias is
//            pre-seeded in the lo half; final fold = lo+hi per output.
// ---------------------------------------------------------------------------
__global__ __launch_bounds__(256, 2) void edge_kernel(const float* __restrict__ nodes,
                                                      float* __restrict__ out) {
    extern __shared__ float smem[];
    float* xs   = smem;                    // [MB][16]       64KB
    float* T2sm = smem + MB * 16;          // [IG][256]       4KB
    float* sbe  = T2sm + IG * 256;         // [16]

    const int tid = threadIdx.x;
    const int b   = blockIdx.x >> 8;       // 256 i-groups per batch
    const int ig  = blockIdx.x & 255;
    const int i0  = ig * IG;

    // ---- Phase 0: stage batch X into shared ----
    const float4* __restrict__ Xg = (const float4*)(nodes + (size_t)b * (MB * 16));
    float4* xs4 = (float4*)xs;
#pragma unroll
    for (int k = 0; k < 16; ++k) xs4[tid + k * 256] = Xg[tid + k * 256];
    if (tid < 16) sbe[tid] = g_beff[tid];
    __syncthreads();

    // ---- Phase 1: T for 4 i's, pair-interleaved over e ----
    {
        const int e = tid >> 4, o = tid & 15;
        float t0 = 0.f, t1 = 0.f, t2 = 0.f, t3 = 0.f;
#pragma unroll
        for (int d = 0; d < 16; ++d) {
            float w = g_WT[d * 256 + tid];
            t0 += xs[(i0 + 0) * 16 + d] * w;
            t1 += xs[(i0 + 1) * 16 + d] * w;
            t2 += xs[(i0 + 2) * 16 + d] * w;
            t3 += xs[(i0 + 3) * 16 + d] * w;
        }
        const int po = (e >> 1) * 32 + o * 2 + (e & 1);
        T2sm[0 * 256 + po] = t0;
        T2sm[1 * 256 + po] = t1;
        T2sm[2 * 256 + po] = t2;
        T2sm[3 * 256 + po] = t3;
    }
    __syncthreads();

    // ---- Phase 2: edges, dual-stream, e-pair packed ----
    const int lane = tid & 31;
    const int warp = tid >> 5;
    const int q    = lane & 3;             // o-quad: outputs [4q, 4q+4)
    const int slot = lane >> 2;            // j-slot within warp (0..7)

    // bias in lo half, 0 in hi: final lo+hi fold includes bias exactly once
    const unsigned long long bias0 = pack2(sbe[4 * q + 0], 0.f);
    const unsigned long long bias1 = pack2(sbe[4 * q + 1], 0.f);
    const unsigned long long bias2v = pack2(sbe[4 * q + 2], 0.f);
    const unsigned long long bias3 = pack2(sbe[4 * q + 3], 0.f);

    const ulonglong2* __restrict__ X2 = (const ulonglong2*)xs;   // 16B units
    const int jb = warp * 128 + slot;      // stream A base; B = A + 64
    const ulonglong2* __restrict__ xwA = X2 + (size_t)jb * 4;
    const ulonglong2* __restrict__ xwB = xwA + 64 * 4;

#pragma unroll 1
    for (int ii = 0; ii < IG; ++ii) {
        const int i = i0 + ii;

        // T2 for this lane's o-quad -> 32 u64 registers
        unsigned long long Ta[8], Tb[8], Tc[8], Td[8];
#pragma unroll
        for (int ep = 0; ep < 8; ++ep) {
            const float* base = T2sm + ii * 256 + ep * 32 + q * 8;
            ulonglong2 u = *(const ulonglong2*)(base);
            ulonglong2 v = *(const ulonglong2*)(base + 4);
            Ta[ep] = u.x; Tb[ep] = u.y; Tc[ep] = v.x; Td[ep] = v.y;
        }

        float* __restrict__ outBase =
            out + (size_t)(b * MB + i) * (MB - 1) * 16 + q * 4;

#pragma unroll 1
        for (int jj = 0; jj < 8; ++jj) {
            const int jA = jb + jj * 8;    // stream A
            const int jB = jA + 64;        // stream B

            // ALL loads first: 8 LDS.128, x pairs arrive pre-packed
            ulonglong2 a0 = xwA[jj * 32 + 0];
            ulonglong2 a1 = xwA[jj * 32 + 1];
            ulonglong2 a2 = xwA[jj * 32 + 2];
            ulonglong2 a3 = xwA[jj * 32 + 3];
            ulonglong2 b0 = xwB[jj * 32 + 0];
            ulonglong2 b1 = xwB[jj * 32 + 1];
            ulonglong2 b2 = xwB[jj * 32 + 2];
            ulonglong2 b3v = xwB[jj * 32 + 3];

            unsigned long long A0 = bias0, A1 = bias1, A2 = bias2v, A3 = bias3;
            unsigned long long B0 = bias0, B1 = bias1, B2 = bias2v, B3 = bias3;

            // 8 interleaved FFMA2 chains, zero packing
#pragma unroll
            for (int ep = 0; ep < 8; ++ep) {
                unsigned long long xA =
                    (ep < 2) ? (ep & 1 ? a0.y : a0.x) :
                    (ep < 4) ? (ep & 1 ? a1.y : a1.x) :
                    (ep < 6) ? (ep & 1 ? a2.y : a2.x) :
                               (ep & 1 ? a3.y : a3.x);
                unsigned long long xB =
                    (ep < 2) ? (ep & 1 ? b0.y : b0.x) :
                    (ep < 4) ? (ep & 1 ? b1.y : b1.x) :
                    (ep < 6) ? (ep & 1 ? b2.y : b2.x) :
                               (ep & 1 ? b3v.y : b3v.x);
                A0 = ffma2(Ta[ep], xA, A0);
                A1 = ffma2(Tb[ep], xA, A1);
                A2 = ffma2(Tc[ep], xA, A2);
                A3 = ffma2(Td[ep], xA, A3);
                B0 = ffma2(Ta[ep], xB, B0);
                B1 = ffma2(Tb[ep], xB, B1);
                B2 = ffma2(Tc[ep], xB, B2);
                B3 = ffma2(Td[ep], xB, B3);
            }

            if (jA != i) {
                const int r = jA - (jA > i);
                float2 f0 = unpack2(A0), f1 = unpack2(A1);
                float2 f2 = unpack2(A2), f3 = unpack2(A3);
                *(float4*)(outBase + (size_t)r * 16) =
                    make_float4(f0.x + f0.y, f1.x + f1.y,
                                f2.x + f2.y, f3.x + f3.y);
            }
            if (jB != i) {
                const int r = jB - (jB > i);
                float2 f0 = unpack2(B0), f1 = unpack2(B1);
                float2 f2 = unpack2(B2), f3 = unpack2(B3);
                *(float4*)(outBase + (size_t)r * 16) =
                    make_float4(f0.x + f0.y, f1.x + f1.y,
                                f2.x + f2.y, f3.x + f3.y);
            }
        }
    }
}

extern "C" void kernel_launch(void* const* d_in, const int* in_sizes, int n_in,
                              void* d_out, int out_size) {
    const float* nodes = (const float*)d_in[0];
    const float* W_bil = (const float*)d_in[1];
    const float* b_bil = (const float*)d_in[2];
    const float* W2    = (const float*)d_in[3];
    const float* b2    = (const float*)d_in[4];
    const float* W3    = (const float*)d_in[5];
    const float* b3    = (const float*)d_in[6];
    float* out = (float*)d_out;

    const int smem_bytes = (MB * 16 + IG * 256 + 16) * (int)sizeof(float);
    static bool attr_set = false;
    if (!attr_set) {
        cudaFuncSetAttribute(edge_kernel,
                             cudaFuncAttributeMaxDynamicSharedMemorySize,
                             smem_bytes);
        attr_set = true;
    }

    prep_kernel<<<1, 256>>>(W_bil, b_bil, W2, b2, W3, b3);
    edge_kernel<<<NB * (MB / IG), 256, smem_bytes>>>(nodes, out);
}